// round 16
// baseline (speedup 1.0000x reference)
#include <cuda_runtime.h>

#define NCLS 19
#define CH   32
#define IN_H 128
#define IN_W 128
#define OUT_H 512
#define OUT_W 512
#define NB   4
#define TPAD 67   // tile col stride: (3c+x)%32 -> conflict-free across lanes

__device__ float    g_S1[NB * NCLS * CH];   // zero-init at load; self-cleaned
__device__ float    g_S2[NB * NCLS * CH];
__device__ int      g_cnt[NB * NCLS];
__device__ unsigned g_done;

// ---------------------------------------------------------------------------
// Fully fused, 256-thread CTAs: 8 warps = 8 output rows (one octet) x half.
// Tile: 4 input rows serve all 8 output rows. NO reg clamp (R15 lesson).
__global__ void __launch_bounds__(256) main_kernel(const float* __restrict__ emb,
                                                   const int*   __restrict__ label,
                                                   float* __restrict__ out) {
    __shared__ float    tile[4][CH][TPAD];                          // 34304 B
    __shared__ __align__(16) unsigned char raw[8 * NCLS * CH * 8];  // 38912 B
    __shared__ unsigned slab[8][64];                                // 2048 B
    __shared__ int      whist[8][NCLS];
    __shared__ unsigned s_last;
    float2 (*s)[NCLS * CH] = reinterpret_cast<float2 (*)[NCLS * CH]>(raw);

    const int tid  = threadIdx.x;
    const int w    = tid >> 5;
    const int lane = tid & 31;
    const int bx   = blockIdx.x;
    const int n    = bx >> 7;            // 4 batches
    const int rem  = bx & 127;
    const int m    = rem >> 1;           // 64 row-octets (rows 8m..8m+7)
    const int half = rem & 1;
    const int y    = 8 * m + w;          // warp's output row
    const int g0   = half * 64;          // first 4-px group of this half

    // ---- stage labels (packed 4x8bit per group word) + zero hist ----
    {
        const int4* lp = (const int4*)(label + ((size_t)(n * OUT_H + y) * OUT_W)) + g0;
        int4 L0 = lp[lane];
        int4 L1 = lp[lane + 32];
        slab[w][lane]      = (unsigned)L0.x | ((unsigned)L0.y << 8) |
                             ((unsigned)L0.z << 16) | ((unsigned)L0.w << 24);
        slab[w][lane + 32] = (unsigned)L1.x | ((unsigned)L1.y << 8) |
                             ((unsigned)L1.z << 16) | ((unsigned)L1.w << 24);
        for (int i = lane; i < NCLS; i += 32) whist[w][i] = 0;
    }

    // ---- tile load: input rows 2m-1..2m+2 (clamped), cols g0-1..g0+64 ----
    {
        const float* eb   = emb + (size_t)n * (CH * IN_H * IN_W);
        const int    c    = lane;        // channel
        const int    chnk = w;           // 8 col-chunks of 8 cols
        #pragma unroll
        for (int rr = 0; rr < 4; ++rr) {
            int row = 2 * m - 1 + rr;
            row = row < 0 ? 0 : (row > IN_H - 1 ? IN_H - 1 : row);
            const float* srcr = eb + ((size_t)c * IN_H + row) * IN_W;
            const float4* src = (const float4*)(srcr + g0 + chnk * 8);
            float4 v0 = src[0], v1 = src[1];
            float* dr = &tile[rr][c][0];
            int x = 1 + chnk * 8;
            dr[x]     = v0.x; dr[x + 1] = v0.y; dr[x + 2] = v0.z; dr[x + 3] = v0.w;
            dr[x + 4] = v1.x; dr[x + 5] = v1.y; dr[x + 6] = v1.z; dr[x + 7] = v1.w;
            if (chnk == 0) {
                int cl = g0 - 1; cl = cl < 0 ? 0 : cl;
                dr[0] = srcr[cl];
            } else if (chnk == 1) {
                int cr = g0 + 64; cr = cr > IN_W - 1 ? IN_W - 1 : cr;
                dr[65] = srcr[cr];
            }
        }
    }

    // ---- zero bins ----
    for (int i = tid; i < 8 * NCLS * CH / 2; i += 256)
        ((float4*)raw)[i] = make_float4(0.f, 0.f, 0.f, 0.f);
    __syncthreads();

    // ---- hot loop (branch-free, pure smem) ----
    const float fy = 0.125f + 0.25f * (float)((w + 2) & 3);
    const int   rA = ((w >> 1) + 1) >> 1;    // {0,0,1,1,1,1,2,2}
    const float* tAp = &tile[rA][lane][0];
    const float* tBp = &tile[rA + 1][lane][0];
    float2* __restrict__ sbl = s[w] + lane;

    auto bin = [&](int k, float v) {
        float2* p = sbl + k * CH;
        float2 o = *p;
        o.x += v;
        o.y = fmaf(v, v, o.y);
        *p = o;
    };

    float a0 = tAp[0], b0 = tBp[0];
    float yvA = fmaf(fy, b0 - a0, a0);   // col g0-1 (clamped at load)
    float a1 = tAp[1], b1 = tBp[1];
    float yvB = fmaf(fy, b1 - a1, a1);   // col g0

    #pragma unroll 4
    for (int t = 0; t < 64; ++t) {
        float a = tAp[t + 2], b = tBp[t + 2];   // col g0+t+1 (edge preclamped)
        float yvC = fmaf(fy, b - a, a);
        unsigned Lp = slab[w][t];
        float d0 = yvB - yvA;
        float d1 = yvC - yvB;
        bin((int)(Lp & 0xffu),         fmaf(0.625f, d0, yvA));
        bin((int)((Lp >> 8) & 0xffu),  fmaf(0.875f, d0, yvA));
        bin((int)((Lp >> 16) & 0xffu), fmaf(0.125f, d1, yvB));
        bin((int)(Lp >> 24),           fmaf(0.375f, d1, yvB));
        yvA = yvB; yvB = yvC;
    }

    // ---- fused histogram: warp counts its own 256 staged labels ----
    #pragma unroll
    for (int it = 0; it < 8; ++it) {
        unsigned word = slab[w][it * 8 + (lane >> 2)];
        int k = (int)((word >> ((lane & 3) * 8)) & 0xffu);
        unsigned mm = __match_any_sync(0xffffffffu, k);
        if (lane == (__ffs(mm) - 1)) whist[w][k] += __popc(mm);
    }
    __syncthreads();

    // ---- reduce 8 warp copies -> global atomics ----
    for (int i = tid; i < NCLS * CH; i += 256) {
        float a = 0.f, b = 0.f;
        #pragma unroll
        for (int ww = 0; ww < 8; ++ww) { float2 v = s[ww][i]; a += v.x; b += v.y; }
        atomicAdd(&g_S1[n * NCLS * CH + i], a);
        atomicAdd(&g_S2[n * NCLS * CH + i], b);
    }
    if (tid < NCLS) {
        int c = 0;
        #pragma unroll
        for (int ww = 0; ww < 8; ++ww) c += whist[ww][tid];
        atomicAdd(&g_cnt[n * NCLS + tid], c);
    }

    __threadfence();
    if (tid == 0) s_last = (atomicAdd(&g_done, 1u) == (unsigned)(gridDim.x - 1));
    __syncthreads();
    if (!s_last) return;

    // ---------------- epilogue (last CTA, reuses bin smem) ----------------
    struct Epi {
        float cnt[NB][NCLS];
        float mu[NB][NCLS][CH];
        float intra[NB][NCLS];
        float interp[NB][2];
        float nfg[NB];
        float l2i[NB];
    };
    Epi* e = reinterpret_cast<Epi*>(raw);
    __syncthreads();

    if (tid < NB * NCLS)
        e->cnt[tid / NCLS][tid % NCLS] = (float)g_cnt[tid];
    __syncthreads();

    {   // per-class mean + intra (warp pair per batch)
        int nn = w >> 1, sub = w & 1;
        for (int k = sub; k < NCLS; k += 2) {
            float cn = e->cnt[nn][k];
            float s1 = __ldcg(&g_S1[nn * NCLS * CH + k * CH + lane]);
            float s2 = __ldcg(&g_S2[nn * NCLS * CH + k * CH + lane]);
            float mu = s1 / (cn + 1.0f);
            e->mu[nn][k][lane] = mu;
            float t2 = s2 + mu * fmaf(cn, mu, -2.0f * s1);
            #pragma unroll
            for (int o = 16; o; o >>= 1) t2 += __shfl_xor_sync(0xffffffffu, t2, o);
            if (lane == 0) e->intra[nn][k] = t2 / ((float)CH * (cn + 1.0f));
        }
    }
    __syncthreads();

    // self-clean accumulators for the next graph replay (all reads done)
    for (int i = tid; i < NB * NCLS * CH; i += 256) { g_S1[i] = 0.f; g_S2[i] = 0.f; }
    if (tid < NB * NCLS) g_cnt[tid] = 0;
    if (tid == 0) g_done = 0u;

    if (tid < NB) {
        float nf = 0.f, li = 0.f;
        for (int k = 1; k < NCLS; ++k)
            if (e->cnt[tid][k] > 0.f) { nf += 1.f; li += e->intra[tid][k]; }
        e->nfg[tid] = nf;
        e->l2i[tid] = li / nf;
    }
    __syncthreads();

    {   // inter: masked pairwise mean-squared distances (warp pair per batch)
        int nn = w >> 1, sub = w & 1;
        float acc = 0.f;
        for (int p = sub; p < NCLS * NCLS; p += 2) {
            int j = p / NCLS, k = p - j * NCLS;
            if (j >= 1 && k >= 1 && e->cnt[nn][j] > 0.f && e->cnt[nn][k] > 0.f) {
                float d = e->mu[nn][j][lane] - e->mu[nn][k][lane];
                acc = fmaf(d, d, acc);
            }
        }
        #pragma unroll
        for (int o = 16; o; o >>= 1) acc += __shfl_xor_sync(0xffffffffu, acc, o);
        if (lane == 0) e->interp[nn][sub] = acc / (float)CH;
    }
    __syncthreads();

    if (tid < NB) {
        float inter = e->interp[tid][0] + e->interp[tid][1];
        out[tid] = e->l2i[tid] - inter / (e->nfg[tid] * e->nfg[tid]);
    }
}

// ---------------------------------------------------------------------------
extern "C" void kernel_launch(void* const* d_in, const int* in_sizes, int n_in,
                              void* d_out, int out_size) {
    const float* emb   = (const float*)d_in[0];   // (4,32,128,128) f32
    const int*   label = (const int*)d_in[1];     // (4,512,512) int32
    float*       out   = (float*)d_out;           // (4,) f32

    main_kernel<<<NB * 64 * 2, 256>>>(emb, label, out);
}

// round 17
// speedup vs baseline: 1.2714x; 1.2714x over previous
#include <cuda_runtime.h>

#define NCLS 19
#define CH   32
#define IN_H 128
#define IN_W 128
#define OUT_H 512
#define OUT_W 512
#define NB   4

__device__ float    g_S1[NB * NCLS * CH];   // zero-init at load; self-cleaned
__device__ float    g_S2[NB * NCLS * CH];
__device__ int      g_cnt[NB * NCLS];
__device__ unsigned g_done;

// ---------------------------------------------------------------------------
// Fully fused, 128-thread CTAs (R14 shape), smem trimmed under 45KB -> 5 CTA/SM.
// Tile layout [row][x][c]: no pad needed, conflict-free both directions.
__global__ void __launch_bounds__(128) main_kernel(const float* __restrict__ emb,
                                                   const int*   __restrict__ label,
                                                   float* __restrict__ out) {
    __shared__ float    tileF[3 * 66 * 32];                         // 25344 B
    __shared__ __align__(16) unsigned char raw[4 * NCLS * CH * 8];  // 19456 B
    __shared__ unsigned slab[4][64];                                // 1024 B
    float2 (*s)[NCLS * CH] = reinterpret_cast<float2 (*)[NCLS * CH]>(raw);
    // slab doubles (after histogram) as per-warp count stash + s_last flag

    const int tid  = threadIdx.x;
    const int w    = tid >> 5;
    const int lane = tid & 31;
    const int bx   = blockIdx.x;
    const int n    = bx >> 8;            // 4 batches
    const int q    = (bx >> 1) & 127;    // 128 row-quads
    const int half = bx & 1;
    const int y    = 4 * q + w;
    const int g0   = half * 64;          // first input column of this half

    // ---- stage labels (packed 4x8bit per group word) ----
    {
        const int4* lp = (const int4*)(label + ((size_t)(n * OUT_H + y) * OUT_W)) + g0;
        int4 L0 = lp[lane];
        int4 L1 = lp[lane + 32];
        slab[w][lane]      = (unsigned)L0.x | ((unsigned)L0.y << 8) |
                             ((unsigned)L0.z << 16) | ((unsigned)L0.w << 24);
        slab[w][lane + 32] = (unsigned)L1.x | ((unsigned)L1.y << 8) |
                             ((unsigned)L1.z << 16) | ((unsigned)L1.w << 24);
    }

    // ---- tile load: rows q-1,q,q+1 (clamped), x=0..65 <-> cols g0-1..g0+64 ----
    // tile(rr,x,c) = tileF[(rr*66 + x)*32 + c]; lane = channel c.
    {
        const int c    = lane;
        const int sgrp = w;              // 4 chunks of 16 x-positions
        const float* eb = emb + (size_t)n * (CH * IN_H * IN_W);
        #pragma unroll
        for (int rr = 0; rr < 3; ++rr) {
            int row = q - 1 + rr;
            row = row < 0 ? 0 : (row > IN_H - 1 ? IN_H - 1 : row);
            const float* srcr = eb + ((size_t)c * IN_H + row) * IN_W;
            const float4* src = (const float4*)(srcr + g0 + 16 * sgrp);
            float* dr = &tileF[(rr * 66) * 32 + c];
            #pragma unroll
            for (int i = 0; i < 4; ++i) {
                float4 v = src[i];
                int x = 1 + 16 * sgrp + 4 * i;
                dr[x * 32]       = v.x;
                dr[(x + 1) * 32] = v.y;
                dr[(x + 2) * 32] = v.z;
                dr[(x + 3) * 32] = v.w;
            }
            if (sgrp == 0) {
                int cl = g0 - 1; cl = cl < 0 ? 0 : cl;
                dr[0] = srcr[cl];
            } else if (sgrp == 1) {
                int cr = g0 + 64; cr = cr > IN_W - 1 ? IN_W - 1 : cr;
                dr[65 * 32] = srcr[cr];
            }
        }
    }

    // ---- zero bins ----
    for (int i = tid; i < 4 * NCLS * CH / 2; i += 128)
        ((float4*)raw)[i] = make_float4(0.f, 0.f, 0.f, 0.f);
    __syncthreads();

    // ---- hot loop (branch-free, pure smem; byte-equivalent to R14) ----
    const float fy = 0.125f + 0.25f * (float)((w + 2) & 3);
    const int   rA = w >> 1;             // w=0,1 -> rows(0,1); w=2,3 -> rows(1,2)
    const float* tAp = &tileF[(rA * 66) * 32 + lane];
    const float* tBp = tAp + 66 * 32;
    float2* __restrict__ sbl = s[w] + lane;

    auto bin = [&](int k, float v) {
        float2* p = sbl + k * CH;
        float2 o = *p;
        o.x += v;
        o.y = fmaf(v, v, o.y);
        *p = o;
    };

    float a0 = tAp[0], b0 = tBp[0];
    float yvA = fmaf(fy, b0 - a0, a0);       // x=0: col g0-1 (clamped at load)
    float a1 = tAp[32], b1 = tBp[32];
    float yvB = fmaf(fy, b1 - a1, a1);       // x=1: col g0

    #pragma unroll 4
    for (int t = 0; t < 64; ++t) {
        float a = tAp[(t + 2) * 32], b = tBp[(t + 2) * 32];
        float yvC = fmaf(fy, b - a, a);
        unsigned Lp = slab[w][t];
        float d0 = yvB - yvA;
        float d1 = yvC - yvB;
        bin((int)(Lp & 0xffu),         fmaf(0.625f, d0, yvA));
        bin((int)((Lp >> 8) & 0xffu),  fmaf(0.875f, d0, yvA));
        bin((int)((Lp >> 16) & 0xffu), fmaf(0.125f, d1, yvB));
        bin((int)(Lp >> 24),           fmaf(0.375f, d1, yvB));
        yvA = yvB; yvB = yvC;
    }

    // ---- histogram in registers via ballot; stash into own slab region ----
    {
        int cnt = 0;
        #pragma unroll
        for (int it = 0; it < 8; ++it) {
            unsigned word = slab[w][it * 8 + (lane >> 2)];
            int k = (int)((word >> ((lane & 3) * 8)) & 0xffu);
            #pragma unroll
            for (int cls = 0; cls < NCLS; ++cls) {
                unsigned mm = __ballot_sync(0xffffffffu, k == cls);
                if (lane == cls) cnt += __popc(mm);
            }
        }
        __syncwarp();                       // all lanes done reading slab[w]
        if (lane < NCLS) slab[w][lane] = (unsigned)cnt;   // warp-private stash
    }
    __syncthreads();

    // ---- reduce 4 warp copies -> global atomics ----
    for (int i = tid; i < NCLS * CH; i += 128) {
        float a = 0.f, b = 0.f;
        #pragma unroll
        for (int ww = 0; ww < 4; ++ww) { float2 v = s[ww][i]; a += v.x; b += v.y; }
        atomicAdd(&g_S1[n * NCLS * CH + i], a);
        atomicAdd(&g_S2[n * NCLS * CH + i], b);
    }
    if (tid < NCLS) {
        int c = (int)(slab[0][tid] + slab[1][tid] + slab[2][tid] + slab[3][tid]);
        atomicAdd(&g_cnt[n * NCLS + tid], c);
    }

    __threadfence();
    if (tid == 0)
        slab[0][63] = (atomicAdd(&g_done, 1u) == (unsigned)(gridDim.x - 1));
    __syncthreads();
    if (!slab[0][63]) return;

    // ---------------- epilogue (last CTA, reuses bin smem) ----------------
    struct Epi {
        float cnt[NB][NCLS];
        float mu[NB][NCLS][CH];
        float intra[NB][NCLS];
        float inter[NB];
        float nfg[NB];
        float l2i[NB];
    };
    Epi* e = reinterpret_cast<Epi*>(raw);
    __syncthreads();

    if (tid < NB * NCLS)
        e->cnt[tid / NCLS][tid % NCLS] = (float)g_cnt[tid];
    __syncthreads();

    {   // warp w = batch w: per-class mean + intra
        for (int k = 0; k < NCLS; ++k) {
            float cn = e->cnt[w][k];
            float s1 = __ldcg(&g_S1[w * NCLS * CH + k * CH + lane]);
            float s2 = __ldcg(&g_S2[w * NCLS * CH + k * CH + lane]);
            float m  = s1 / (cn + 1.0f);
            e->mu[w][k][lane] = m;
            float t2 = s2 + m * fmaf(cn, m, -2.0f * s1);
            #pragma unroll
            for (int o = 16; o; o >>= 1) t2 += __shfl_xor_sync(0xffffffffu, t2, o);
            if (lane == 0) e->intra[w][k] = t2 / ((float)CH * (cn + 1.0f));
        }
    }
    __syncthreads();

    // self-clean accumulators for the next graph replay (all reads done)
    for (int i = tid; i < NB * NCLS * CH; i += 128) { g_S1[i] = 0.f; g_S2[i] = 0.f; }
    if (tid < NB * NCLS) g_cnt[tid] = 0;
    if (tid == 0) g_done = 0u;

    if (tid < NB) {
        float nf = 0.f, li = 0.f;
        for (int k = 1; k < NCLS; ++k)
            if (e->cnt[tid][k] > 0.f) { nf += 1.f; li += e->intra[tid][k]; }
        e->nfg[tid] = nf;
        e->l2i[tid] = li / nf;
    }
    __syncthreads();

    {   // warp w = batch w: inter-class pairwise distances
        float acc = 0.f;
        for (int j = 1; j < NCLS; ++j) {
            if (e->cnt[w][j] <= 0.f) continue;
            float mj = e->mu[w][j][lane];
            for (int k = 1; k < NCLS; ++k) {
                if (e->cnt[w][k] > 0.f) {
                    float d = mj - e->mu[w][k][lane];
                    acc = fmaf(d, d, acc);
                }
            }
        }
        #pragma unroll
        for (int o = 16; o; o >>= 1) acc += __shfl_xor_sync(0xffffffffu, acc, o);
        if (lane == 0) e->inter[w] = acc / (float)CH;
    }
    __syncthreads();

    if (tid < NB)
        out[tid] = e->l2i[tid] - e->inter[tid] / (e->nfg[tid] * e->nfg[tid]);
}

// ---------------------------------------------------------------------------
extern "C" void kernel_launch(void* const* d_in, const int* in_sizes, int n_in,
                              void* d_out, int out_size) {
    const float* emb   = (const float*)d_in[0];   // (4,32,128,128) f32
    const int*   label = (const int*)d_in[1];     // (4,512,512) int32
    float*       out   = (float*)d_out;           // (4,) f32

    main_kernel<<<NB * 128 * 2, 128>>>(emb, label, out);
}